// round 2
// baseline (speedup 1.0000x reference)
#include <cuda_runtime.h>
#include <cstdint>

// Problem constants (fixed by setup_inputs)
#define BB 8
#define NN 60
#define LL 21504
#define CC 15
#define TK 13
#define BGI 15
#define FEPS 1e-9f

static constexpr int BL = BB * LL;   // 172032
static constexpr int BN = BB * NN;   // 480

// ---------------- scratch (device globals; no allocation) ----------------
__device__ float4   g_paabb[BL];     // pred AABB: x=mnx y=mxx z=mny w=mxy
__device__ float    g_parea[BL];
__device__ float4   g_gaabb[BN];
__device__ float    g_garea[BN];
__device__ float    g_gcos[BN], g_gsin[BN];
__device__ float    g_gcx[BN], g_gcy[BN], g_gw2[BN], g_gh2[BN];
__device__ int      g_glabel[BN];
__device__ int      g_gcrowd[BN];
__device__ float    g_gpad[BN];
__device__ int      g_sum[BL];       // per-anchor positive count (pre-replacement)
__device__ int      g_tmpg[BL];      // unique gt when sum==1
__device__ int      g_asg[BL];       // final assigned gt
__device__ float    g_amv[BL];       // am at assigned gt
__device__ unsigned g_maxam[BN];     // float bits, values >= 0
__device__ unsigned g_maxiou[BN];

// ---------------- helpers ----------------
__device__ __forceinline__ void box_aabb(float cx, float cy, float w, float h, float r,
                                         float& mnx, float& mxx, float& mny, float& mxy) {
    float c = cosf(r), s = sinf(r);
    float dx = w * 0.5f * c;
    float dy = h * 0.5f * s;
    float xc[4] = {cx - dx, cx + dx, cx + dx, cx - dx};
    float yc[4] = {cy - dy, cy - dy, cy + dy, cy + dy};
    mnx = 1e30f; mxx = -1e30f; mny = 1e30f; mxy = -1e30f;
#pragma unroll
    for (int k = 0; k < 4; ++k) {
        float ddx = xc[k] - cx;
        float ddy = yc[k] - cy;
        float xr = cx + ddx * c - ddy * s;
        float yr = cy + ddx * s + ddy * c;
        mnx = fminf(mnx, xr); mxx = fmaxf(mxx, xr);
        mny = fminf(mny, yr); mxy = fmaxf(mxy, yr);
    }
}

__device__ __forceinline__ float iou_ab(float4 A, float aA, float4 B, float aB) {
    float iw = fminf(A.y, B.y) - fmaxf(A.x, B.x);
    iw = fmaxf(iw, 0.0f);
    float ih = fminf(A.w, B.w) - fmaxf(A.z, B.z);
    ih = fmaxf(ih, 0.0f);
    float inter = iw * ih;
    float iou = inter / (aA + aB - inter + FEPS);
    return fminf(fmaxf(iou, 0.0f), 1.0f);
}

__device__ __forceinline__ float pow6(float x) {
    float p2 = x * x;
    float p4 = p2 * p2;
    return p2 * p4;
}

__device__ __forceinline__ bool pt_inside(float px, float py, float cx, float cy,
                                          float c, float s, float w2, float h2) {
    float dx = px - cx, dy = py - cy;
    float xl = dx * c + dy * s;
    float yl = -dx * s + dy * c;
    return (fabsf(xl) <= w2) && (fabsf(yl) <= h2);
}

// ---------------- K0: zero scratch ----------------
__global__ void k_zero() {
    int i = blockIdx.x * blockDim.x + threadIdx.x;
    if (i < BL) g_sum[i] = 0;
    if (i < BN) { g_maxam[i] = 0u; g_maxiou[i] = 0u; }
}

// ---------------- K1: pred AABB precompute ----------------
__global__ void k_pred(const float* __restrict__ prb) {
    int i = blockIdx.x * blockDim.x + threadIdx.x;
    if (i >= BL) return;
    const float* p = prb + (size_t)i * 5;
    float cx = p[0], cy = p[1], w = p[2], h = p[3], r = p[4];
    float mnx, mxx, mny, mxy;
    box_aabb(cx, cy, w, h, r, mnx, mxx, mny, mxy);
    g_paabb[i] = make_float4(mnx, mxx, mny, mxy);
    g_parea[i] = w * h;
}

// ---------------- K2: gt precompute ----------------
// glab32: gt_labels buffer viewed as int32 words. The harness converts int64
// inputs to int32 (per stub type list); if it ever keeps int64, all odd words
// are the (zero) high halves -> detect and index accordingly.
__global__ void k_gt(const float* __restrict__ gtb, const int* __restrict__ glab32,
                     const int* __restrict__ gcrowd, const float* __restrict__ gpad) {
    int i = blockIdx.x * blockDim.x + threadIdx.x;
    if (i >= BN) return;

    bool is64 = true;
    for (int j = 1; j < BN; j += 2) {
        if (glab32[j] != 0) { is64 = false; break; }
    }
    int lab = is64 ? glab32[2 * i] : glab32[i];
    lab = min(max(lab, 0), CC - 1);   // crash-guard

    const float* p = gtb + (size_t)i * 5;
    float cx = p[0], cy = p[1], w = p[2], h = p[3], r = p[4];
    float mnx, mxx, mny, mxy;
    box_aabb(cx, cy, w, h, r, mnx, mxx, mny, mxy);
    g_gaabb[i] = make_float4(mnx, mxx, mny, mxy);
    g_garea[i] = w * h;
    g_gcos[i] = cosf(r);
    g_gsin[i] = sinf(r);
    g_gcx[i] = cx; g_gcy[i] = cy;
    g_gw2[i] = w * 0.5f; g_gh2[i] = h * 0.5f;
    g_glabel[i] = lab;
    g_gcrowd[i] = gcrowd[i];
    g_gpad[i] = gpad[i];
}

// ---------------- K3: per-(b,gt) top-13 + scatter ----------------
__global__ void __launch_bounds__(256) k_topk(const float* __restrict__ scores,
                                              const float* __restrict__ anch) {
    const int bi = blockIdx.x;         // b*NN + i
    const int b = bi / NN;
    const int gi = bi % NN;
    const int tid = threadIdx.x;

    __shared__ float sg[9];            // aabb(4), area, cos, sin, cx, cy
    __shared__ float sw2, sh2, spad;
    __shared__ int slab;
    if (tid == 0) {
        float4 a = g_gaabb[bi];
        sg[0] = a.x; sg[1] = a.y; sg[2] = a.z; sg[3] = a.w;
        sg[4] = g_garea[bi];
        sg[5] = g_gcos[bi]; sg[6] = g_gsin[bi];
        sg[7] = g_gcx[bi];  sg[8] = g_gcy[bi];
        sw2 = g_gw2[bi]; sh2 = g_gh2[bi];
        slab = g_glabel[bi];
        spad = g_gpad[bi];
    }
    __syncthreads();
    if (spad == 0.0f) return;          // padded gt contributes nothing

    const float4 ga = make_float4(sg[0], sg[1], sg[2], sg[3]);
    const float garea = sg[4], gc = sg[5], gs = sg[6], gcx = sg[7], gcy = sg[8];
    const float w2 = sw2, h2 = sh2;
    const int lab = slab;
    const size_t sbase = (size_t)b * LL * CC;
    const int pbase = b * LL;

    unsigned long long loc[TK];
#pragma unroll
    for (int k = 0; k < TK; ++k) loc[k] = 0ull;

    for (int l = tid; l < LL; l += 256) {
        float4 pa = g_paabb[pbase + l];
        float iou = iou_ab(ga, garea, pa, g_parea[pbase + l]);
        float sc = scores[sbase + (size_t)l * CC + lab];
        float am = sc * pow6(iou);
        float px = anch[2 * l], py = anch[2 * l + 1];
        bool ing = pt_inside(px, py, gcx, gcy, gc, gs, w2, h2);
        float metric = ing ? am : 0.0f;
        unsigned long long key =
            ((unsigned long long)__float_as_uint(metric) << 32) |
            (unsigned long long)(0xFFFFFFFFu - (unsigned)l);
        if (key > loc[0]) {
            int j = 0;
#pragma unroll
            for (; j < TK - 1; ++j) {
                if (key > loc[j + 1]) loc[j] = loc[j + 1];
                else break;
            }
            loc[j] = key;
        }
    }

    __shared__ unsigned long long cand[256 * TK];
    __shared__ unsigned long long red[256];
#pragma unroll
    for (int k = 0; k < TK; ++k) cand[tid * TK + k] = loc[k];
    __syncthreads();

    for (int r = 0; r < TK; ++r) {
        unsigned long long m = 0ull;
#pragma unroll
        for (int k = 0; k < TK; ++k) {
            unsigned long long v = cand[tid * TK + k];
            m = (v > m) ? v : m;
        }
        red[tid] = m;
        __syncthreads();
        for (int off = 128; off > 0; off >>= 1) {
            if (tid < off) {
                unsigned long long a = red[tid], bb2 = red[tid + off];
                red[tid] = (bb2 > a) ? bb2 : a;
            }
            __syncthreads();
        }
        unsigned long long w = red[0];
#pragma unroll
        for (int k = 0; k < TK; ++k)
            if (cand[tid * TK + k] == w) cand[tid * TK + k] = 0ull;
        if (tid == 0 && w != 0ull) {
            unsigned anchor = 0xFFFFFFFFu - (unsigned)(w & 0xFFFFFFFFull);
            unsigned mb = (unsigned)(w >> 32);
            if (anchor < (unsigned)LL) {
                bool pos;
                if (mb != 0u) {
                    pos = true;   // metric>0 implies inside gt
                } else {
                    float px = anch[2 * anchor], py = anch[2 * anchor + 1];
                    pos = pt_inside(px, py, gcx, gcy, gc, gs, w2, h2);
                }
                if (pos) {
                    atomicAdd(&g_sum[pbase + anchor], 1);
                    g_tmpg[pbase + anchor] = gi;   // valid iff final count==1
                }
            }
        }
        __syncthreads();
    }
}

// ---------------- K4: per-anchor assignment + per-gt maxes ----------------
__global__ void k_assign(const float* __restrict__ scores) {
    int idx = blockIdx.x * blockDim.x + threadIdx.x;
    if (idx >= BL) return;
    int b = idx / LL;
    int s = g_sum[idx];
    if (s == 0) {
        g_asg[idx] = 0;
        g_amv[idx] = 0.0f;
        return;
    }
    float4 pa = g_paabb[idx];
    float parea = g_parea[idx];
    int g;
    if (s == 1) {
        g = g_tmpg[idx];
    } else {
        float best = -1.0f;
        g = 0;
        for (int i = 0; i < NN; ++i) {
            int gi = b * NN + i;
            float iou = iou_ab(g_gaabb[gi], g_garea[gi], pa, parea);
            if (iou > best) { best = iou; g = i; }
        }
    }
    int gg = b * NN + g;
    float iou = iou_ab(g_gaabb[gg], g_garea[gg], pa, parea);
    float sc = scores[(size_t)idx * CC + g_glabel[gg]];
    float am = sc * pow6(iou);
    g_asg[idx] = g;
    g_amv[idx] = am;
    atomicMax(&g_maxam[gg], __float_as_uint(am));
    atomicMax(&g_maxiou[gg], __float_as_uint(iou));
}

// ---------------- K5: outputs ----------------
__global__ void k_out(const float* __restrict__ gtb, float* __restrict__ out) {
    int idx = blockIdx.x * blockDim.x + threadIdx.x;
    if (idx >= BL) return;
    int b = idx / LL;
    int s = g_sum[idx];
    int g = g_asg[idx];      // 0 when s==0
    int gg = b * NN + g;
    int crowd = g_gcrowd[gg];
    int lbl = BGI;
    float per = 0.0f;
    if (s > 0) {
        lbl = g_glabel[gg];
        float mm = __uint_as_float(g_maxam[gg]);
        float mi = __uint_as_float(g_maxiou[gg]);
        per = g_amv[idx] / (mm + FEPS) * mi;
    }
    float cm = (crowd == 0) ? 1.0f : 0.0f;

    float* o_lab = out;                      // BL
    float* o_rb  = out + BL;                 // BL*5
    float* o_sc  = o_rb + (size_t)BL * 5;    // BL*15
    float* o_gi  = o_sc + (size_t)BL * 15;   // BL
    float* o_cr  = o_gi + BL;                // BL

    o_lab[idx] = (float)lbl;
    const float* gb = gtb + (size_t)gg * 5;
#pragma unroll
    for (int k = 0; k < 5; ++k) o_rb[(size_t)idx * 5 + k] = gb[k];
#pragma unroll
    for (int c = 0; c < CC; ++c) o_sc[(size_t)idx * CC + c] = 0.0f;
    if (s > 0 && lbl < CC) o_sc[(size_t)idx * CC + lbl] = per * cm;
    o_gi[idx] = (float)g;
    o_cr[idx] = (float)crowd;
}

// ---------------- launch ----------------
extern "C" void kernel_launch(void* const* d_in, const int* in_sizes, int n_in,
                              void* d_out, int out_size) {
    const float* pred_scores = (const float*)d_in[0];
    const float* pred_rboxes = (const float*)d_in[1];
    const float* anchors     = (const float*)d_in[2];
    const int*   gt_labels32 = (const int*)d_in[3];   // int64 downcast by harness (hedged in k_gt)
    const float* gt_bboxes   = (const float*)d_in[4];
    // d_in[5] = gt_poses (unused)
    const int*   gt_crowd    = (const int*)d_in[6];
    const float* pad_mask    = (const float*)d_in[7];
    float*       out         = (float*)d_out;

    const int T = 256;
    k_zero<<<(BL + T - 1) / T, T>>>();
    k_pred<<<(BL + T - 1) / T, T>>>(pred_rboxes);
    k_gt<<<(BN + T - 1) / T, T>>>(gt_bboxes, gt_labels32, gt_crowd, pad_mask);
    k_topk<<<BN, 256>>>(pred_scores, anchors);
    k_assign<<<(BL + T - 1) / T, T>>>(pred_scores);
    k_out<<<(BL + T - 1) / T, T>>>(gt_bboxes, out);
}

// round 3
// speedup vs baseline: 1.1618x; 1.1618x over previous
#include <cuda_runtime.h>
#include <cstdint>

#define BB 8
#define NN 60
#define LL 21504
#define CC 15
#define TK 13
#define BGI 15
#define FEPS 1e-9f

static constexpr int BL = BB * LL;   // 172032
static constexpr int BN = BB * NN;   // 480
static constexpr int CAP = 256 * TK; // 3328 candidate capacity

// ---------------- scratch ----------------
__device__ float4   g_paabb[BL];
__device__ float    g_parea[BL];
__device__ float4   g_gaabb[BN];
__device__ float    g_garea[BN];
__device__ float    g_gcos[BN], g_gsin[BN];
__device__ float    g_gcx[BN], g_gcy[BN], g_gw2[BN], g_gh2[BN];
__device__ int      g_glabel[BN];
__device__ int      g_gcrowd[BN];
__device__ float    g_gpad[BN];
__device__ int      g_sum[BL];
__device__ int      g_tmpg[BL];
__device__ int      g_asg[BL];
__device__ float    g_amv[BL];
__device__ unsigned g_maxam[BN];
__device__ unsigned g_maxiou[BN];

// ---------------- helpers ----------------
__device__ __forceinline__ void box_aabb(float cx, float cy, float w, float h, float r,
                                         float& mnx, float& mxx, float& mny, float& mxy) {
    float c = cosf(r), s = sinf(r);
    float dx = w * 0.5f * c;
    float dy = h * 0.5f * s;
    float xc[4] = {cx - dx, cx + dx, cx + dx, cx - dx};
    float yc[4] = {cy - dy, cy - dy, cy + dy, cy + dy};
    mnx = 1e30f; mxx = -1e30f; mny = 1e30f; mxy = -1e30f;
#pragma unroll
    for (int k = 0; k < 4; ++k) {
        float ddx = xc[k] - cx;
        float ddy = yc[k] - cy;
        float xr = cx + ddx * c - ddy * s;
        float yr = cy + ddx * s + ddy * c;
        mnx = fminf(mnx, xr); mxx = fmaxf(mxx, xr);
        mny = fminf(mny, yr); mxy = fmaxf(mxy, yr);
    }
}

__device__ __forceinline__ float iou_ab(float4 A, float aA, float4 B, float aB) {
    float iw = fminf(A.y, B.y) - fmaxf(A.x, B.x);
    iw = fmaxf(iw, 0.0f);
    float ih = fminf(A.w, B.w) - fmaxf(A.z, B.z);
    ih = fmaxf(ih, 0.0f);
    float inter = iw * ih;
    float iou = inter / (aA + aB - inter + FEPS);
    return fminf(fmaxf(iou, 0.0f), 1.0f);
}

__device__ __forceinline__ float pow6(float x) {
    float p2 = x * x;
    float p4 = p2 * p2;
    return p2 * p4;
}

__device__ __forceinline__ bool pt_inside(float px, float py, float cx, float cy,
                                          float c, float s, float w2, float h2) {
    float dx = px - cx, dy = py - cy;
    float xl = dx * c + dy * s;
    float yl = -dx * s + dy * c;
    return (fabsf(xl) <= w2) && (fabsf(yl) <= h2);
}

__device__ __forceinline__ void insert13(unsigned long long* loc, unsigned long long key) {
    if (key > loc[0]) {
        int j = 0;
#pragma unroll
        for (; j < TK - 1; ++j) {
            if (key > loc[j + 1]) loc[j] = loc[j + 1];
            else break;
        }
        loc[j] = key;
    }
}

// ---------------- K1: zero + pred AABB ----------------
__global__ void k_prep(const float* __restrict__ prb) {
    int i = blockIdx.x * blockDim.x + threadIdx.x;
    if (i >= BL) return;
    g_sum[i] = 0;
    if (i < BN) { g_maxam[i] = 0u; g_maxiou[i] = 0u; }
    const float* p = prb + (size_t)i * 5;
    float cx = p[0], cy = p[1], w = p[2], h = p[3], r = p[4];
    float mnx, mxx, mny, mxy;
    box_aabb(cx, cy, w, h, r, mnx, mxx, mny, mxy);
    g_paabb[i] = make_float4(mnx, mxx, mny, mxy);
    g_parea[i] = w * h;
}

// ---------------- K2: gt precompute ----------------
__global__ void k_gt(const float* __restrict__ gtb, const int* __restrict__ glab32,
                     const int* __restrict__ gcrowd, const float* __restrict__ gpad) {
    int i = blockIdx.x * blockDim.x + threadIdx.x;
    if (i >= BN) return;

    bool is64 = true;
    for (int j = 1; j < BN; j += 2) {
        if (glab32[j] != 0) { is64 = false; break; }
    }
    int lab = is64 ? glab32[2 * i] : glab32[i];
    lab = min(max(lab, 0), CC - 1);

    const float* p = gtb + (size_t)i * 5;
    float cx = p[0], cy = p[1], w = p[2], h = p[3], r = p[4];
    float mnx, mxx, mny, mxy;
    box_aabb(cx, cy, w, h, r, mnx, mxx, mny, mxy);
    g_gaabb[i] = make_float4(mnx, mxx, mny, mxy);
    g_garea[i] = w * h;
    g_gcos[i] = cosf(r);
    g_gsin[i] = sinf(r);
    g_gcx[i] = cx; g_gcy[i] = cy;
    g_gw2[i] = w * 0.5f; g_gh2[i] = h * 0.5f;
    g_glabel[i] = lab;
    g_gcrowd[i] = gcrowd[i];
    g_gpad[i] = gpad[i];
}

// ---------------- K3: per-(b,gt) top-13 + scatter ----------------
__global__ void __launch_bounds__(256) k_topk(const float* __restrict__ scores,
                                              const float* __restrict__ anch) {
    const int bi = blockIdx.x;
    const int b = bi / NN;
    const int gi = bi % NN;
    const int tid = threadIdx.x;

    __shared__ float sg[9];
    __shared__ float sw2, sh2, spad;
    __shared__ int slab;
    __shared__ int scount;
    __shared__ unsigned long long sbuf[CAP];

    if (tid == 0) {
        float4 a = g_gaabb[bi];
        sg[0] = a.x; sg[1] = a.y; sg[2] = a.z; sg[3] = a.w;
        sg[4] = g_garea[bi];
        sg[5] = g_gcos[bi]; sg[6] = g_gsin[bi];
        sg[7] = g_gcx[bi];  sg[8] = g_gcy[bi];
        sw2 = g_gw2[bi]; sh2 = g_gh2[bi];
        slab = g_glabel[bi];
        spad = g_gpad[bi];
        scount = 0;
    }
    __syncthreads();
    if (spad == 0.0f) return;

    const float4 ga = make_float4(sg[0], sg[1], sg[2], sg[3]);
    const float garea = sg[4], gc = sg[5], gs = sg[6], gcx = sg[7], gcy = sg[8];
    const float w2 = sw2, h2 = sh2;
    const int lab = slab;
    const size_t sbase = (size_t)b * LL * CC;
    const int pbase = b * LL;
    const float2* anch2 = (const float2*)anch;

    unsigned long long loc[TK];
#pragma unroll
    for (int k = 0; k < TK; ++k) loc[k] = 0ull;

    // Phase 1: positives only (metric > 0 requires inside-gt)
    for (int l = tid; l < LL; l += 256) {
        float2 pt = anch2[l];
        if (!pt_inside(pt.x, pt.y, gcx, gcy, gc, gs, w2, h2)) continue;
        float4 pa = g_paabb[pbase + l];
        float iou = iou_ab(ga, garea, pa, g_parea[pbase + l]);
        float sc = scores[sbase + (size_t)l * CC + lab];
        float am = sc * pow6(iou);
        if (am <= 0.0f) continue;
        unsigned long long key =
            ((unsigned long long)__float_as_uint(am) << 32) |
            (unsigned long long)(0xFFFFFFFFu - (unsigned)l);
        insert13(loc, key);
    }

    // Compact nonzero keys into shared buffer
    int cnt = 0;
#pragma unroll
    for (int k = 0; k < TK; ++k) if (loc[k] != 0ull) cnt++;
    if (cnt > 0) {
        int base = atomicAdd(&scount, cnt);
        int j = 0;
#pragma unroll
        for (int k = 0; k < TK; ++k)
            if (loc[k] != 0ull) sbuf[base + j++] = loc[k];
    }
    __syncthreads();
    if (tid >= 32) return;

    // Phase 2: warp 0 selects global top-13 (shfl, no barriers)
    const unsigned FULL = 0xFFFFFFFFu;
    int n = scount;
    unsigned long long w13[TK];
#pragma unroll
    for (int k = 0; k < TK; ++k) w13[k] = 0ull;
    for (int i = tid; i < n; i += 32) insert13(w13, sbuf[i]);

    int fillc = 0;
    for (int r = 0; r < TK; ++r) {
        unsigned long long m = w13[TK - 1];
#pragma unroll
        for (int off = 16; off > 0; off >>= 1) {
            unsigned long long o = __shfl_xor_sync(FULL, m, off);
            m = (o > m) ? o : m;
        }
        if (m == 0ull) { fillc = TK - r; break; }
        bool own = (w13[TK - 1] == m);
        unsigned ob = __ballot_sync(FULL, own);
        if (tid == (__ffs(ob) - 1)) {   // pop my max
#pragma unroll
            for (int k = TK - 1; k > 0; --k) w13[k] = w13[k - 1];
            w13[0] = 0ull;
        }
        if (tid == 0) {
            unsigned anchor = 0xFFFFFFFFu - (unsigned)(m & 0xFFFFFFFFull);
            atomicAdd(&g_sum[pbase + anchor], 1);
            g_tmpg[pbase + anchor] = gi;
        }
    }

    // Phase 3: zero-metric fillers. If P < 13 then fillers are the first
    // (13-P) zero-metric anchor indices; among indices 0..31 at most P <= 12
    // are positive, so fillers always lie in {0..31}.
    if (fillc > 0) {
        int l = tid;
        float2 pt = anch2[l];
        bool ins = pt_inside(pt.x, pt.y, gcx, gcy, gc, gs, w2, h2);
        bool zero = true;
        if (ins) {
            float4 pa = g_paabb[pbase + l];
            float iou = iou_ab(ga, garea, pa, g_parea[pbase + l]);
            float sc = scores[sbase + (size_t)l * CC + lab];
            zero = (sc * pow6(iou) <= 0.0f);
        }
        unsigned zm = __ballot_sync(FULL, zero);
        unsigned im = __ballot_sync(FULL, ins);
        if (tid == 0) {
            for (int c = 0; c < fillc && zm; ++c) {
                int bpos = __ffs(zm) - 1;
                zm &= zm - 1;
                if ((im >> bpos) & 1u) {   // in-topk filler that is inside gt
                    atomicAdd(&g_sum[pbase + bpos], 1);
                    g_tmpg[pbase + bpos] = gi;
                }
            }
        }
    }
}

// ---------------- K4: per-anchor assignment + per-gt maxes ----------------
__global__ void k_assign(const float* __restrict__ scores) {
    int idx = blockIdx.x * blockDim.x + threadIdx.x;
    if (idx >= BL) return;
    int b = idx / LL;
    int s = g_sum[idx];
    if (s == 0) {
        g_asg[idx] = 0;
        g_amv[idx] = 0.0f;
        return;
    }
    float4 pa = g_paabb[idx];
    float parea = g_parea[idx];
    int g;
    if (s == 1) {
        g = g_tmpg[idx];
    } else {
        float best = -1.0f;
        g = 0;
        for (int i = 0; i < NN; ++i) {
            int gi = b * NN + i;
            float iou = iou_ab(g_gaabb[gi], g_garea[gi], pa, parea);
            if (iou > best) { best = iou; g = i; }
        }
    }
    int gg = b * NN + g;
    float iou = iou_ab(g_gaabb[gg], g_garea[gg], pa, parea);
    float sc = scores[(size_t)idx * CC + g_glabel[gg]];
    float am = sc * pow6(iou);
    g_asg[idx] = g;
    g_amv[idx] = am;
    atomicMax(&g_maxam[gg], __float_as_uint(am));
    atomicMax(&g_maxiou[gg], __float_as_uint(iou));
}

// ---------------- K5: outputs ----------------
__global__ void k_out(const float* __restrict__ gtb, float* __restrict__ out) {
    int idx = blockIdx.x * blockDim.x + threadIdx.x;
    if (idx >= BL) return;
    int b = idx / LL;
    int s = g_sum[idx];
    int g = g_asg[idx];
    int gg = b * NN + g;
    int crowd = g_gcrowd[gg];
    int lbl = BGI;
    float per = 0.0f;
    if (s > 0) {
        lbl = g_glabel[gg];
        float mm = __uint_as_float(g_maxam[gg]);
        float mi = __uint_as_float(g_maxiou[gg]);
        per = g_amv[idx] / (mm + FEPS) * mi;
    }
    float cm = (crowd == 0) ? 1.0f : 0.0f;

    float* o_lab = out;
    float* o_rb  = out + BL;
    float* o_sc  = o_rb + (size_t)BL * 5;
    float* o_gi  = o_sc + (size_t)BL * 15;
    float* o_cr  = o_gi + BL;

    o_lab[idx] = (float)lbl;
    const float* gb = gtb + (size_t)gg * 5;
#pragma unroll
    for (int k = 0; k < 5; ++k) o_rb[(size_t)idx * 5 + k] = gb[k];
#pragma unroll
    for (int c = 0; c < CC; ++c) o_sc[(size_t)idx * CC + c] = 0.0f;
    if (s > 0 && lbl < CC) o_sc[(size_t)idx * CC + lbl] = per * cm;
    o_gi[idx] = (float)g;
    o_cr[idx] = (float)crowd;
}

// ---------------- launch ----------------
extern "C" void kernel_launch(void* const* d_in, const int* in_sizes, int n_in,
                              void* d_out, int out_size) {
    const float* pred_scores = (const float*)d_in[0];
    const float* pred_rboxes = (const float*)d_in[1];
    const float* anchors     = (const float*)d_in[2];
    const int*   gt_labels32 = (const int*)d_in[3];
    const float* gt_bboxes   = (const float*)d_in[4];
    const int*   gt_crowd    = (const int*)d_in[6];
    const float* pad_mask    = (const float*)d_in[7];
    float*       out         = (float*)d_out;

    const int T = 256;
    k_prep<<<(BL + T - 1) / T, T>>>(pred_rboxes);
    k_gt<<<(BN + T - 1) / T, T>>>(gt_bboxes, gt_labels32, gt_crowd, pad_mask);
    k_topk<<<BN, 256>>>(pred_scores, anchors);
    k_assign<<<(BL + T - 1) / T, T>>>(pred_scores);
    k_out<<<(BL + T - 1) / T, T>>>(gt_bboxes, out);
}

// round 7
// speedup vs baseline: 2.6449x; 2.2766x over previous
#include <cuda_runtime.h>
#include <cstdint>

#define BB 8
#define NN 60
#define LL 21504
#define CC 15
#define TK 13
#define BGI 15
#define FEPS 1e-9f

static constexpr int BL = BB * LL;   // 172032
static constexpr int BN = BB * NN;   // 480
static constexpr int CAP = 256 * TK; // candidate capacity in k_topk
static constexpr int PLCAP = 8192;   // positive list capacity (max real 6240)

// ---------------- scratch ----------------
__device__ float4   g_paabb[BL];
__device__ float    g_parea[BL];
__device__ float4   g_gaabb[BN];     // reference-style AABB (for IoU only!)
__device__ float    g_garea[BN];
__device__ float    g_gcos[BN], g_gsin[BN];
__device__ float    g_gcx[BN], g_gcy[BN], g_gw2[BN], g_gh2[BN];
__device__ int      g_glabel[BN];
__device__ int      g_gcrowd[BN];
__device__ float    g_gpad[BN];
__device__ int      g_sum[BL];
__device__ int      g_tmpg[BL];
__device__ int      g_asg[BL];
__device__ float    g_amv[BL];
__device__ unsigned g_maxam[BN];
__device__ unsigned g_maxiou[BN];
__device__ int      g_npos;
__device__ int      g_plist[PLCAP];

// ---------------- helpers ----------------
__device__ __forceinline__ void box_aabb(float cx, float cy, float w, float h, float r,
                                         float& mnx, float& mxx, float& mny, float& mxy) {
    float c = cosf(r), s = sinf(r);
    float dx = w * 0.5f * c;
    float dy = h * 0.5f * s;
    float xc[4] = {cx - dx, cx + dx, cx + dx, cx - dx};
    float yc[4] = {cy - dy, cy - dy, cy + dy, cy + dy};
    mnx = 1e30f; mxx = -1e30f; mny = 1e30f; mxy = -1e30f;
#pragma unroll
    for (int k = 0; k < 4; ++k) {
        float ddx = xc[k] - cx;
        float ddy = yc[k] - cy;
        float xr = cx + ddx * c - ddy * s;
        float yr = cy + ddx * s + ddy * c;
        mnx = fminf(mnx, xr); mxx = fmaxf(mxx, xr);
        mny = fminf(mny, yr); mxy = fmaxf(mxy, yr);
    }
}

__device__ __forceinline__ float iou_ab(float4 A, float aA, float4 B, float aB) {
    float iw = fminf(A.y, B.y) - fmaxf(A.x, B.x);
    iw = fmaxf(iw, 0.0f);
    float ih = fminf(A.w, B.w) - fmaxf(A.z, B.z);
    ih = fmaxf(ih, 0.0f);
    float inter = iw * ih;
    float iou = inter / (aA + aB - inter + FEPS);
    return fminf(fmaxf(iou, 0.0f), 1.0f);
}

__device__ __forceinline__ float pow6(float x) {
    float p2 = x * x;
    float p4 = p2 * p2;
    return p2 * p4;
}

__device__ __forceinline__ bool pt_inside(float px, float py, float cx, float cy,
                                          float c, float s, float w2, float h2) {
    float dx = px - cx, dy = py - cy;
    float xl = dx * c + dy * s;
    float yl = -dx * s + dy * c;
    return (fabsf(xl) <= w2) && (fabsf(yl) <= h2);
}

__device__ __forceinline__ void insert13(unsigned long long* loc, unsigned long long key) {
    if (key > loc[0]) {
        int j = 0;
#pragma unroll
        for (; j < TK - 1; ++j) {
            if (key > loc[j + 1]) loc[j] = loc[j + 1];
            else break;
        }
        loc[j] = key;
    }
}

// ---------------- K1: zero + pred AABB + gt precompute ----------------
__global__ void k_pre(const float* __restrict__ prb, const float* __restrict__ gtb,
                      const int* __restrict__ glab32, const int* __restrict__ gcrowd,
                      const float* __restrict__ gpad) {
    int i = blockIdx.x * blockDim.x + threadIdx.x;
    if (i >= BL) return;
    g_sum[i] = 0;
    if (i == 0) g_npos = 0;

    {
        const float* p = prb + (size_t)i * 5;
        float cx = p[0], cy = p[1], w = p[2], h = p[3], r = p[4];
        float mnx, mxx, mny, mxy;
        box_aabb(cx, cy, w, h, r, mnx, mxx, mny, mxy);
        g_paabb[i] = make_float4(mnx, mxx, mny, mxy);
        g_parea[i] = w * h;
    }

    if (i < BN) {
        g_maxam[i] = 0u; g_maxiou[i] = 0u;
        bool is64 = true;
        for (int j = 1; j < BN; j += 2) {
            if (glab32[j] != 0) { is64 = false; break; }
        }
        int lab = is64 ? glab32[2 * i] : glab32[i];
        lab = min(max(lab, 0), CC - 1);

        const float* p = gtb + (size_t)i * 5;
        float cx = p[0], cy = p[1], w = p[2], h = p[3], r = p[4];
        float mnx, mxx, mny, mxy;
        box_aabb(cx, cy, w, h, r, mnx, mxx, mny, mxy);
        g_gaabb[i] = make_float4(mnx, mxx, mny, mxy);
        g_garea[i] = w * h;
        g_gcos[i] = cosf(r);
        g_gsin[i] = sinf(r);
        g_gcx[i] = cx; g_gcy[i] = cy;
        g_gw2[i] = w * 0.5f; g_gh2[i] = h * 0.5f;
        g_glabel[i] = lab;
        g_gcrowd[i] = gcrowd[i];
        g_gpad[i] = gpad[i];
    }
}

// ---------------- K2: per-(b,gt) top-13 + scatter ----------------
// Anchor grid levels: stride 8 (128x128, base 0), 16 (64x64, base 16384), 32 (32x32, base 20480)
__constant__ int   c_lG[3]    = {128, 64, 32};
__constant__ int   c_lbase[3] = {0, 16384, 20480};
__constant__ float c_ls[3]    = {8.0f, 16.0f, 32.0f};

__global__ void __launch_bounds__(256) k_topk(const float* __restrict__ scores,
                                              const float* __restrict__ anch) {
    const int bi = blockIdx.x;
    const int b = bi / NN;
    const int gi = bi % NN;
    const int tid = threadIdx.x;

    __shared__ float sg[9];
    __shared__ float sw2, sh2, spad;
    __shared__ int slab;
    __shared__ int scount;
    __shared__ unsigned long long sbuf[CAP];

    if (tid == 0) {
        float4 a = g_gaabb[bi];
        sg[0] = a.x; sg[1] = a.y; sg[2] = a.z; sg[3] = a.w;
        sg[4] = g_garea[bi];
        sg[5] = g_gcos[bi]; sg[6] = g_gsin[bi];
        sg[7] = g_gcx[bi];  sg[8] = g_gcy[bi];
        sw2 = g_gw2[bi]; sh2 = g_gh2[bi];
        slab = g_glabel[bi];
        spad = g_gpad[bi];
        scount = 0;
    }
    __syncthreads();
    if (spad == 0.0f) return;

    const float4 ga = make_float4(sg[0], sg[1], sg[2], sg[3]);
    const float garea = sg[4], gc = sg[5], gs = sg[6], gcx = sg[7], gcy = sg[8];
    const float w2 = sw2, h2 = sh2;
    const int lab = slab;
    const size_t sbase = (size_t)b * LL * CC;
    const int pbase = b * LL;
    const float2* anch2 = (const float2*)anch;

    // TRUE containment bound for the rbox interior (NOT the reference-style
    // AABB, which does not contain the rbox): |px-cx| <= Ex, |py-cy| <= Ey.
    const float Ex = w2 * fabsf(gc) + h2 * fabsf(gs);
    const float Ey = w2 * fabsf(gs) + h2 * fabsf(gc);
    const float rx0 = gcx - Ex, rx1 = gcx + Ex;
    const float ry0 = gcy - Ey, ry1 = gcy + Ey;

    unsigned long long loc[TK];
#pragma unroll
    for (int k = 0; k < TK; ++k) loc[k] = 0ull;

    // Phase 1: scan only grid cells inside the (padded) true-extent rect.
    for (int lev = 0; lev < 3; ++lev) {
        const float st = c_ls[lev];
        const int G = c_lG[lev];
        const int base = c_lbase[lev];
        const float inv = 1.0f / st;
        int ix0 = max(0, (int)floorf(rx0 * inv - 0.5f) - 1);
        int ix1 = min(G - 1, (int)ceilf(rx1 * inv - 0.5f) + 1);
        int iy0 = max(0, (int)floorf(ry0 * inv - 0.5f) - 1);
        int iy1 = min(G - 1, (int)ceilf(ry1 * inv - 0.5f) + 1);
        int nx = ix1 - ix0 + 1;
        int ny = iy1 - iy0 + 1;
        if (nx <= 0 || ny <= 0) continue;
        int tot = nx * ny;
        for (int t = tid; t < tot; t += 256) {
            int iy = iy0 + t / nx;
            int ix = ix0 + t - (t / nx) * nx;
            float px = ((float)ix + 0.5f) * st;
            float py = ((float)iy + 0.5f) * st;
            if (!pt_inside(px, py, gcx, gcy, gc, gs, w2, h2)) continue;
            int l = base + iy * G + ix;
            float4 pa = g_paabb[pbase + l];
            float iou = iou_ab(ga, garea, pa, g_parea[pbase + l]);
            float sc = scores[sbase + (size_t)l * CC + lab];
            float am = sc * pow6(iou);
            if (am <= 0.0f) continue;
            unsigned long long key =
                ((unsigned long long)__float_as_uint(am) << 32) |
                (unsigned long long)(0xFFFFFFFFu - (unsigned)l);
            insert13(loc, key);
        }
    }

    // Compact nonzero keys
    int cnt = 0;
#pragma unroll
    for (int k = 0; k < TK; ++k) if (loc[k] != 0ull) cnt++;
    if (cnt > 0) {
        int base = atomicAdd(&scount, cnt);
        int j = 0;
#pragma unroll
        for (int k = 0; k < TK; ++k)
            if (loc[k] != 0ull) sbuf[base + j++] = loc[k];
    }
    __syncthreads();
    if (tid >= 32) return;

    // Phase 2: warp 0 selects global top-13
    const unsigned FULL = 0xFFFFFFFFu;
    int n = scount;
    unsigned long long w13[TK];
#pragma unroll
    for (int k = 0; k < TK; ++k) w13[k] = 0ull;
    for (int i = tid; i < n; i += 32) insert13(w13, sbuf[i]);

    int fillc = 0;
    for (int r = 0; r < TK; ++r) {
        unsigned long long m = w13[TK - 1];
#pragma unroll
        for (int off = 16; off > 0; off >>= 1) {
            unsigned long long o = __shfl_xor_sync(FULL, m, off);
            m = (o > m) ? o : m;
        }
        if (m == 0ull) { fillc = TK - r; break; }
        bool own = (w13[TK - 1] == m);
        unsigned ob = __ballot_sync(FULL, own);
        if (tid == (__ffs(ob) - 1)) {
#pragma unroll
            for (int k = TK - 1; k > 0; --k) w13[k] = w13[k - 1];
            w13[0] = 0ull;
        }
        if (tid == 0) {
            unsigned anchor = 0xFFFFFFFFu - (unsigned)(m & 0xFFFFFFFFull);
            int a = pbase + anchor;
            int old = atomicAdd(&g_sum[a], 1);
            g_tmpg[a] = gi;
            if (old == 0) {
                int p = atomicAdd(&g_npos, 1);
                if (p < PLCAP) g_plist[p] = a;
            }
        }
    }

    // Phase 3: zero-metric fillers (always within anchor indices 0..31)
    if (fillc > 0) {
        int l = tid;
        float2 pt = anch2[l];
        bool ins = pt_inside(pt.x, pt.y, gcx, gcy, gc, gs, w2, h2);
        bool zero = true;
        if (ins) {
            float4 pa = g_paabb[pbase + l];
            float iou = iou_ab(ga, garea, pa, g_parea[pbase + l]);
            float sc = scores[sbase + (size_t)l * CC + lab];
            zero = (sc * pow6(iou) <= 0.0f);
        }
        unsigned zm = __ballot_sync(FULL, zero);
        unsigned im = __ballot_sync(FULL, ins);
        if (tid == 0) {
            for (int c = 0; c < fillc && zm; ++c) {
                int bpos = __ffs(zm) - 1;
                zm &= zm - 1;
                if ((im >> bpos) & 1u) {
                    int a = pbase + bpos;
                    int old = atomicAdd(&g_sum[a], 1);
                    g_tmpg[a] = gi;
                    if (old == 0) {
                        int p = atomicAdd(&g_npos, 1);
                        if (p < PLCAP) g_plist[p] = a;
                    }
                }
            }
        }
    }
}

// ---------------- K3: warp-per-positive assignment ----------------
__global__ void __launch_bounds__(256) k_assign(const float* __restrict__ scores) {
    int gtid = blockIdx.x * blockDim.x + threadIdx.x;
    int wi = gtid >> 5;
    int lane = gtid & 31;
    int np = g_npos;
    if (wi >= np) return;
    int a = g_plist[wi];
    int b = a / LL;
    int s = g_sum[a];
    float4 pa = g_paabb[a];
    float parea = g_parea[a];

    int g;
    if (s == 1) {
        g = g_tmpg[a];
    } else {
        const unsigned FULL = 0xFFFFFFFFu;
        unsigned long long best = 0ull;
#pragma unroll
        for (int h = 0; h < 2; ++h) {
            int i = lane + h * 32;
            if (i < NN) {
                int gg = b * NN + i;
                float iou = iou_ab(g_gaabb[gg], g_garea[gg], pa, parea);
                unsigned long long key =
                    ((unsigned long long)__float_as_uint(iou) << 32) |
                    (unsigned long long)(63 - i);
                best = (key > best) ? key : best;
            }
        }
#pragma unroll
        for (int off = 16; off > 0; off >>= 1) {
            unsigned long long o = __shfl_xor_sync(FULL, best, off);
            best = (o > best) ? o : best;
        }
        g = 63 - (int)(best & 0xFFFFFFFFull);
    }

    if (lane == 0) {
        int gg = b * NN + g;
        float iou = iou_ab(g_gaabb[gg], g_garea[gg], pa, parea);
        float sc = scores[(size_t)a * CC + g_glabel[gg]];
        float am = sc * pow6(iou);
        g_asg[a] = g;
        g_amv[a] = am;
        atomicMax(&g_maxam[gg], __float_as_uint(am));
        atomicMax(&g_maxiou[gg], __float_as_uint(iou));
    }
}

// ---------------- K4: outputs ----------------
__global__ void k_out(const float* __restrict__ gtb, float* __restrict__ out) {
    int idx = blockIdx.x * blockDim.x + threadIdx.x;
    if (idx >= BL) return;
    int b = idx / LL;
    int s = g_sum[idx];
    int g = (s > 0) ? g_asg[idx] : 0;
    int gg = b * NN + g;
    int crowd = g_gcrowd[gg];
    int lbl = BGI;
    float per = 0.0f;
    if (s > 0) {
        lbl = g_glabel[gg];
        float mm = __uint_as_float(g_maxam[gg]);
        float mi = __uint_as_float(g_maxiou[gg]);
        per = g_amv[idx] / (mm + FEPS) * mi;
    }
    float cm = (crowd == 0) ? 1.0f : 0.0f;

    float* o_lab = out;
    float* o_rb  = out + BL;
    float* o_sc  = o_rb + (size_t)BL * 5;
    float* o_gi  = o_sc + (size_t)BL * 15;
    float* o_cr  = o_gi + BL;

    o_lab[idx] = (float)lbl;
    const float* gb = gtb + (size_t)gg * 5;
#pragma unroll
    for (int k = 0; k < 5; ++k) o_rb[(size_t)idx * 5 + k] = gb[k];
#pragma unroll
    for (int c = 0; c < CC; ++c) o_sc[(size_t)idx * CC + c] = 0.0f;
    if (s > 0 && lbl < CC) o_sc[(size_t)idx * CC + lbl] = per * cm;
    o_gi[idx] = (float)g;
    o_cr[idx] = (float)crowd;
}

// ---------------- launch ----------------
extern "C" void kernel_launch(void* const* d_in, const int* in_sizes, int n_in,
                              void* d_out, int out_size) {
    const float* pred_scores = (const float*)d_in[0];
    const float* pred_rboxes = (const float*)d_in[1];
    const float* anchors     = (const float*)d_in[2];
    const int*   gt_labels32 = (const int*)d_in[3];
    const float* gt_bboxes   = (const float*)d_in[4];
    const int*   gt_crowd    = (const int*)d_in[6];
    const float* pad_mask    = (const float*)d_in[7];
    float*       out         = (float*)d_out;

    const int T = 256;
    k_pre<<<(BL + T - 1) / T, T>>>(pred_rboxes, gt_bboxes, gt_labels32, gt_crowd, pad_mask);
    k_topk<<<BN, 256>>>(pred_scores, anchors);
    k_assign<<<(6240 * 32 + T - 1) / T, T>>>(pred_scores);
    k_out<<<(BL + T - 1) / T, T>>>(gt_bboxes, out);
}

// round 12
// speedup vs baseline: 2.8882x; 1.0920x over previous
#include <cuda_runtime.h>
#include <cstdint>

#define BB 8
#define NN 60
#define LL 21504
#define CC 15
#define TK 13
#define BGI 15
#define FEPS 1e-9f

static constexpr int BL = BB * LL;   // 172032
static constexpr int BN = BB * NN;   // 480
static constexpr int CAP = 256 * TK;
static constexpr int PLCAP = 8192;

// ---------------- scratch ----------------
__device__ float4   g_paabb[BL];
__device__ float    g_parea[BL];
__device__ float4   g_gaabb[BN];     // reference-style AABB (IoU only)
__device__ float    g_garea[BN];
__device__ float    g_gcos[BN], g_gsin[BN];
__device__ float    g_gcx[BN], g_gcy[BN], g_gw2[BN], g_gh2[BN];
__device__ int      g_glabel[BN];
__device__ int      g_gcrowd[BN];
__device__ float    g_gpad[BN];
__device__ int      g_sum[BL];
__device__ int      g_tmpg[BL];
__device__ int      g_asg[BL];
__device__ float    g_amv[BL];
__device__ unsigned g_maxam[BN];
__device__ unsigned g_maxiou[BN];
__device__ int      g_npos;
__device__ int      g_plist[PLCAP];

// ---------------- helpers ----------------
__device__ __forceinline__ void box_aabb(float cx, float cy, float w, float h, float r,
                                         float& mnx, float& mxx, float& mny, float& mxy) {
    float c = cosf(r), s = sinf(r);
    float dx = w * 0.5f * c;
    float dy = h * 0.5f * s;
    float xc[4] = {cx - dx, cx + dx, cx + dx, cx - dx};
    float yc[4] = {cy - dy, cy - dy, cy + dy, cy + dy};
    mnx = 1e30f; mxx = -1e30f; mny = 1e30f; mxy = -1e30f;
#pragma unroll
    for (int k = 0; k < 4; ++k) {
        float ddx = xc[k] - cx;
        float ddy = yc[k] - cy;
        float xr = cx + ddx * c - ddy * s;
        float yr = cy + ddx * s + ddy * c;
        mnx = fminf(mnx, xr); mxx = fmaxf(mxx, xr);
        mny = fminf(mny, yr); mxy = fmaxf(mxy, yr);
    }
}

__device__ __forceinline__ float iou_ab(float4 A, float aA, float4 B, float aB) {
    float iw = fminf(A.y, B.y) - fmaxf(A.x, B.x);
    iw = fmaxf(iw, 0.0f);
    float ih = fminf(A.w, B.w) - fmaxf(A.z, B.z);
    ih = fmaxf(ih, 0.0f);
    float inter = iw * ih;
    float iou = inter / (aA + aB - inter + FEPS);
    return fminf(fmaxf(iou, 0.0f), 1.0f);
}

__device__ __forceinline__ float pow6(float x) {
    float p2 = x * x;
    float p4 = p2 * p2;
    return p2 * p4;
}

__device__ __forceinline__ bool pt_inside(float px, float py, float cx, float cy,
                                          float c, float s, float w2, float h2) {
    float dx = px - cx, dy = py - cy;
    float xl = dx * c + dy * s;
    float yl = -dx * s + dy * c;
    return (fabsf(xl) <= w2) && (fabsf(yl) <= h2);
}

__device__ __forceinline__ void insert13(unsigned long long* loc, unsigned long long key) {
    if (key > loc[0]) {
        int j = 0;
#pragma unroll
        for (; j < TK - 1; ++j) {
            if (key > loc[j + 1]) loc[j] = loc[j + 1];
            else break;
        }
        loc[j] = key;
    }
}

// ---------------- K1: zero + pred AABB + gt precompute ----------------
__global__ void __launch_bounds__(256) k_pre(const float* __restrict__ prb,
                                             const float* __restrict__ gtb,
                                             const int* __restrict__ glab32,
                                             const int* __restrict__ gcrowd,
                                             const float* __restrict__ gpad) {
    __shared__ float sh[256 * 5];
    int i = blockIdx.x * blockDim.x + threadIdx.x;
    // coalesced stage of this block's 256 pred boxes (BL = 672*256 exact)
    {
        int base = blockIdx.x * 256 * 5;
        for (int t = threadIdx.x; t < 256 * 5; t += 256) sh[t] = prb[base + t];
        __syncthreads();
    }
    if (i >= BL) return;
    g_sum[i] = 0;
    if (i == 0) g_npos = 0;

    {
        int t5 = threadIdx.x * 5;
        float cx = sh[t5 + 0], cy = sh[t5 + 1], w = sh[t5 + 2], h = sh[t5 + 3], r = sh[t5 + 4];
        float mnx, mxx, mny, mxy;
        box_aabb(cx, cy, w, h, r, mnx, mxx, mny, mxy);
        g_paabb[i] = make_float4(mnx, mxx, mny, mxy);
        g_parea[i] = w * h;
    }

    if (i < BN) {
        g_maxam[i] = 0u; g_maxiou[i] = 0u;
        bool is64 = true;
        for (int j = 1; j < BN; j += 2) {
            if (glab32[j] != 0) { is64 = false; break; }
        }
        int lab = is64 ? glab32[2 * i] : glab32[i];
        lab = min(max(lab, 0), CC - 1);

        const float* p = gtb + (size_t)i * 5;
        float cx = p[0], cy = p[1], w = p[2], h = p[3], r = p[4];
        float mnx, mxx, mny, mxy;
        box_aabb(cx, cy, w, h, r, mnx, mxx, mny, mxy);
        g_gaabb[i] = make_float4(mnx, mxx, mny, mxy);
        g_garea[i] = w * h;
        g_gcos[i] = cosf(r);
        g_gsin[i] = sinf(r);
        g_gcx[i] = cx; g_gcy[i] = cy;
        g_gw2[i] = w * 0.5f; g_gh2[i] = h * 0.5f;
        g_glabel[i] = lab;
        g_gcrowd[i] = gcrowd[i];
        g_gpad[i] = gpad[i];
    }
}

// ---------------- K2: per-(b,gt) top-13 + scatter ----------------
__constant__ int   c_lG[3]    = {128, 64, 32};
__constant__ int   c_lbase[3] = {0, 16384, 20480};
__constant__ float c_ls[3]    = {8.0f, 16.0f, 32.0f};

__global__ void __launch_bounds__(256) k_topk(const float* __restrict__ scores,
                                              const float* __restrict__ anch) {
    const int bi = blockIdx.x;
    const int b = bi / NN;
    const int gi = bi % NN;
    const int tid = threadIdx.x;

    __shared__ float sg[9];
    __shared__ float sw2, sh2, spad;
    __shared__ int slab;
    __shared__ int scount;
    __shared__ unsigned long long sbuf[CAP];

    if (tid == 0) {
        float4 a = g_gaabb[bi];
        sg[0] = a.x; sg[1] = a.y; sg[2] = a.z; sg[3] = a.w;
        sg[4] = g_garea[bi];
        sg[5] = g_gcos[bi]; sg[6] = g_gsin[bi];
        sg[7] = g_gcx[bi];  sg[8] = g_gcy[bi];
        sw2 = g_gw2[bi]; sh2 = g_gh2[bi];
        slab = g_glabel[bi];
        spad = g_gpad[bi];
        scount = 0;
    }
    __syncthreads();
    if (spad == 0.0f) return;

    const float4 ga = make_float4(sg[0], sg[1], sg[2], sg[3]);
    const float garea = sg[4], gc = sg[5], gs = sg[6], gcx = sg[7], gcy = sg[8];
    const float w2 = sw2, h2 = sh2;
    const int lab = slab;
    const size_t sbase = (size_t)b * LL * CC;
    const int pbase = b * LL;
    const float2* anch2 = (const float2*)anch;

    // TRUE containment extents of the rbox interior
    const float Ex = w2 * fabsf(gc) + h2 * fabsf(gs);
    const float Ey = w2 * fabsf(gs) + h2 * fabsf(gc);
    const float rx0 = gcx - Ex, rx1 = gcx + Ex;
    const float ry0 = gcy - Ey, ry1 = gcy + Ey;

    unsigned long long loc[TK];
#pragma unroll
    for (int k = 0; k < TK; ++k) loc[k] = 0ull;

    for (int lev = 0; lev < 3; ++lev) {
        const float st = c_ls[lev];
        const int G = c_lG[lev];
        const int base = c_lbase[lev];
        const float inv = 1.0f / st;
        int ix0 = max(0, (int)floorf(rx0 * inv - 0.5f) - 1);
        int ix1 = min(G - 1, (int)ceilf(rx1 * inv - 0.5f) + 1);
        int iy0 = max(0, (int)floorf(ry0 * inv - 0.5f) - 1);
        int iy1 = min(G - 1, (int)ceilf(ry1 * inv - 0.5f) + 1);
        int nx = ix1 - ix0 + 1;
        int ny = iy1 - iy0 + 1;
        if (nx <= 0 || ny <= 0) continue;
        int tot = nx * ny;
        for (int t = tid; t < tot; t += 256) {
            int iy = iy0 + t / nx;
            int ix = ix0 + t - (t / nx) * nx;
            float px = ((float)ix + 0.5f) * st;
            float py = ((float)iy + 0.5f) * st;
            if (!pt_inside(px, py, gcx, gcy, gc, gs, w2, h2)) continue;
            int l = base + iy * G + ix;
            float4 pa = g_paabb[pbase + l];
            float iou = iou_ab(ga, garea, pa, g_parea[pbase + l]);
            float sc = scores[sbase + (size_t)l * CC + lab];
            float am = sc * pow6(iou);
            if (am <= 0.0f) continue;
            unsigned long long key =
                ((unsigned long long)__float_as_uint(am) << 32) |
                (unsigned long long)(0xFFFFFFFFu - (unsigned)l);
            insert13(loc, key);
        }
    }

    int cnt = 0;
#pragma unroll
    for (int k = 0; k < TK; ++k) if (loc[k] != 0ull) cnt++;
    if (cnt > 0) {
        int base = atomicAdd(&scount, cnt);
        int j = 0;
#pragma unroll
        for (int k = 0; k < TK; ++k)
            if (loc[k] != 0ull) sbuf[base + j++] = loc[k];
    }
    __syncthreads();
    if (tid >= 32) return;

    const unsigned FULL = 0xFFFFFFFFu;
    int n = scount;
    unsigned long long w13[TK];
#pragma unroll
    for (int k = 0; k < TK; ++k) w13[k] = 0ull;
    for (int i = tid; i < n; i += 32) insert13(w13, sbuf[i]);

    int fillc = 0;
    for (int r = 0; r < TK; ++r) {
        unsigned long long m = w13[TK - 1];
#pragma unroll
        for (int off = 16; off > 0; off >>= 1) {
            unsigned long long o = __shfl_xor_sync(FULL, m, off);
            m = (o > m) ? o : m;
        }
        if (m == 0ull) { fillc = TK - r; break; }
        bool own = (w13[TK - 1] == m);
        unsigned ob = __ballot_sync(FULL, own);
        if (tid == (__ffs(ob) - 1)) {
#pragma unroll
            for (int k = TK - 1; k > 0; --k) w13[k] = w13[k - 1];
            w13[0] = 0ull;
        }
        if (tid == 0) {
            unsigned anchor = 0xFFFFFFFFu - (unsigned)(m & 0xFFFFFFFFull);
            int a = pbase + anchor;
            int old = atomicAdd(&g_sum[a], 1);
            g_tmpg[a] = gi;
            if (old == 0) {
                int p = atomicAdd(&g_npos, 1);
                if (p < PLCAP) g_plist[p] = a;
            }
        }
    }

    if (fillc > 0) {
        int l = tid;
        float2 pt = anch2[l];
        bool ins = pt_inside(pt.x, pt.y, gcx, gcy, gc, gs, w2, h2);
        bool zero = true;
        if (ins) {
            float4 pa = g_paabb[pbase + l];
            float iou = iou_ab(ga, garea, pa, g_parea[pbase + l]);
            float sc = scores[sbase + (size_t)l * CC + lab];
            zero = (sc * pow6(iou) <= 0.0f);
        }
        unsigned zm = __ballot_sync(FULL, zero);
        unsigned im = __ballot_sync(FULL, ins);
        if (tid == 0) {
            for (int c = 0; c < fillc && zm; ++c) {
                int bpos = __ffs(zm) - 1;
                zm &= zm - 1;
                if ((im >> bpos) & 1u) {
                    int a = pbase + bpos;
                    int old = atomicAdd(&g_sum[a], 1);
                    g_tmpg[a] = gi;
                    if (old == 0) {
                        int p = atomicAdd(&g_npos, 1);
                        if (p < PLCAP) g_plist[p] = a;
                    }
                }
            }
        }
    }
}

// ---------------- K3: warp-per-positive assignment ----------------
__global__ void __launch_bounds__(256) k_assign(const float* __restrict__ scores) {
    int gtid = blockIdx.x * blockDim.x + threadIdx.x;
    int wi = gtid >> 5;
    int lane = gtid & 31;
    int np = g_npos;
    if (wi >= np) return;
    int a = g_plist[wi];
    int b = a / LL;
    int s = g_sum[a];
    float4 pa = g_paabb[a];
    float parea = g_parea[a];

    int g;
    if (s == 1) {
        g = g_tmpg[a];
    } else {
        const unsigned FULL = 0xFFFFFFFFu;
        unsigned long long best = 0ull;
#pragma unroll
        for (int h = 0; h < 2; ++h) {
            int i = lane + h * 32;
            if (i < NN) {
                int gg = b * NN + i;
                float iou = iou_ab(g_gaabb[gg], g_garea[gg], pa, parea);
                unsigned long long key =
                    ((unsigned long long)__float_as_uint(iou) << 32) |
                    (unsigned long long)(63 - i);
                best = (key > best) ? key : best;
            }
        }
#pragma unroll
        for (int off = 16; off > 0; off >>= 1) {
            unsigned long long o = __shfl_xor_sync(FULL, best, off);
            best = (o > best) ? o : best;
        }
        g = 63 - (int)(best & 0xFFFFFFFFull);
    }

    if (lane == 0) {
        int gg = b * NN + g;
        float iou = iou_ab(g_gaabb[gg], g_garea[gg], pa, parea);
        float sc = scores[(size_t)a * CC + g_glabel[gg]];
        float am = sc * pow6(iou);
        g_asg[a] = g;
        g_amv[a] = am;
        atomicMax(&g_maxam[gg], __float_as_uint(am));
        atomicMax(&g_maxiou[gg], __float_as_uint(iou));
    }
}

// ---------------- K4: outputs (element-parallel, fully coalesced) ----------------
static constexpr int OUT_ELEMS = BL * 21;  // BL scalars-triple + BL*5 + BL*15

__global__ void __launch_bounds__(256) k_out(const float* __restrict__ gtb,
                                             float* __restrict__ out) {
    int e = blockIdx.x * blockDim.x + threadIdx.x;
    if (e >= OUT_ELEMS) return;

    float* o_lab = out;
    float* o_rb  = out + BL;
    float* o_sc  = o_rb + (size_t)BL * 5;
    float* o_gi  = o_sc + (size_t)BL * 15;
    float* o_cr  = o_gi + BL;

    if (e < BL) {
        // one thread -> lab, gi, cr for anchor e (3 stride-1 coalesced stores)
        int idx = e;
        int b = idx / LL;
        int s = g_sum[idx];
        int g = (s > 0) ? g_asg[idx] : 0;
        int gg = b * NN + g;
        int lbl = (s > 0) ? g_glabel[gg] : BGI;
        o_lab[idx] = (float)lbl;
        o_gi[idx] = (float)g;
        o_cr[idx] = (float)g_gcrowd[gg];
    } else if (e < BL * 6) {
        // rbox elements: thread per float
        int j = e - BL;
        int idx = j / 5;
        int k = j - idx * 5;
        int b = idx / LL;
        int s = g_sum[idx];
        int g = (s > 0) ? g_asg[idx] : 0;
        int gg = b * NN + g;
        o_rb[j] = gtb[(size_t)gg * 5 + k];
    } else {
        // score elements: thread per float
        int j = e - BL * 6;
        int idx = j / 15;
        int c = j - idx * 15;
        int b = idx / LL;
        int s = g_sum[idx];
        float v = 0.0f;
        if (s > 0) {
            int g = g_asg[idx];
            int gg = b * NN + g;
            if (c == g_glabel[gg] && g_gcrowd[gg] == 0) {
                float mm = __uint_as_float(g_maxam[gg]);
                float mi = __uint_as_float(g_maxiou[gg]);
                v = g_amv[idx] / (mm + FEPS) * mi;
            }
        }
        o_sc[j] = v;
    }
}

// ---------------- launch ----------------
extern "C" void kernel_launch(void* const* d_in, const int* in_sizes, int n_in,
                              void* d_out, int out_size) {
    const float* pred_scores = (const float*)d_in[0];
    const float* pred_rboxes = (const float*)d_in[1];
    const float* anchors     = (const float*)d_in[2];
    const int*   gt_labels32 = (const int*)d_in[3];
    const float* gt_bboxes   = (const float*)d_in[4];
    const int*   gt_crowd    = (const int*)d_in[6];
    const float* pad_mask    = (const float*)d_in[7];
    float*       out         = (float*)d_out;

    const int T = 256;
    k_pre<<<(BL + T - 1) / T, T>>>(pred_rboxes, gt_bboxes, gt_labels32, gt_crowd, pad_mask);
    k_topk<<<BN, 256>>>(pred_scores, anchors);
    k_assign<<<(6240 * 32 + T - 1) / T, T>>>(pred_scores);
    k_out<<<(OUT_ELEMS + T - 1) / T, T>>>(gt_bboxes, out);
}

// round 17
// speedup vs baseline: 3.0694x; 1.0628x over previous
#include <cuda_runtime.h>
#include <cstdint>

#define BB 8
#define NN 60
#define LL 21504
#define CC 15
#define TK 13
#define BGI 15
#define FEPS 1e-9f

static constexpr int BL = BB * LL;   // 172032
static constexpr int BN = BB * NN;   // 480
static constexpr int CAP = 256 * TK;
static constexpr int PLCAP = 8192;

// ---------------- scratch ----------------
__device__ float4   g_paabb[BL];
__device__ float    g_parea[BL];
__device__ float4   g_gaabb[BN];     // reference-style AABB (IoU only)
__device__ float    g_garea[BN];
__device__ float    g_gcos[BN], g_gsin[BN];
__device__ float    g_gcx[BN], g_gcy[BN], g_gw2[BN], g_gh2[BN];
__device__ int      g_glabel[BN];
__device__ int      g_gcrowd[BN];
__device__ float    g_gpad[BN];
__device__ int      g_sum[BL];
__device__ int      g_tmpg[BL];
__device__ int      g_asg[BL];
__device__ float    g_amv[BL];
__device__ unsigned g_maxam[BN];
__device__ unsigned g_maxiou[BN];
__device__ int      g_npos;
__device__ int      g_plist[PLCAP];

// ---------------- helpers ----------------
__device__ __forceinline__ void box_aabb(float cx, float cy, float w, float h, float r,
                                         float& mnx, float& mxx, float& mny, float& mxy) {
    float c = cosf(r), s = sinf(r);
    float dx = w * 0.5f * c;
    float dy = h * 0.5f * s;
    float xc[4] = {cx - dx, cx + dx, cx + dx, cx - dx};
    float yc[4] = {cy - dy, cy - dy, cy + dy, cy + dy};
    mnx = 1e30f; mxx = -1e30f; mny = 1e30f; mxy = -1e30f;
#pragma unroll
    for (int k = 0; k < 4; ++k) {
        float ddx = xc[k] - cx;
        float ddy = yc[k] - cy;
        float xr = cx + ddx * c - ddy * s;
        float yr = cy + ddx * s + ddy * c;
        mnx = fminf(mnx, xr); mxx = fmaxf(mxx, xr);
        mny = fminf(mny, yr); mxy = fmaxf(mxy, yr);
    }
}

__device__ __forceinline__ float iou_ab(float4 A, float aA, float4 B, float aB) {
    float iw = fminf(A.y, B.y) - fmaxf(A.x, B.x);
    iw = fmaxf(iw, 0.0f);
    float ih = fminf(A.w, B.w) - fmaxf(A.z, B.z);
    ih = fmaxf(ih, 0.0f);
    float inter = iw * ih;
    float iou = inter / (aA + aB - inter + FEPS);
    return fminf(fmaxf(iou, 0.0f), 1.0f);
}

__device__ __forceinline__ float pow6(float x) {
    float p2 = x * x;
    float p4 = p2 * p2;
    return p2 * p4;
}

__device__ __forceinline__ bool pt_inside(float px, float py, float cx, float cy,
                                          float c, float s, float w2, float h2) {
    float dx = px - cx, dy = py - cy;
    float xl = dx * c + dy * s;
    float yl = -dx * s + dy * c;
    return (fabsf(xl) <= w2) && (fabsf(yl) <= h2);
}

__device__ __forceinline__ void insert13(unsigned long long* loc, unsigned long long key) {
    if (key > loc[0]) {
        int j = 0;
#pragma unroll
        for (; j < TK - 1; ++j) {
            if (key > loc[j + 1]) loc[j] = loc[j + 1];
            else break;
        }
        loc[j] = key;
    }
}

// ---------------- K1: zero + pred AABB + gt precompute ----------------
__global__ void __launch_bounds__(256) k_pre(const float* __restrict__ prb,
                                             const float* __restrict__ gtb,
                                             const int* __restrict__ glab32,
                                             const int* __restrict__ gcrowd,
                                             const float* __restrict__ gpad) {
    __shared__ float sh[256 * 5];
    int i = blockIdx.x * blockDim.x + threadIdx.x;
    {
        int base = blockIdx.x * 256 * 5;
        for (int t = threadIdx.x; t < 256 * 5; t += 256) sh[t] = prb[base + t];
        __syncthreads();
    }
    if (i >= BL) return;
    g_sum[i] = 0;
    if (i == 0) g_npos = 0;

    {
        int t5 = threadIdx.x * 5;
        float cx = sh[t5 + 0], cy = sh[t5 + 1], w = sh[t5 + 2], h = sh[t5 + 3], r = sh[t5 + 4];
        float mnx, mxx, mny, mxy;
        box_aabb(cx, cy, w, h, r, mnx, mxx, mny, mxy);
        g_paabb[i] = make_float4(mnx, mxx, mny, mxy);
        g_parea[i] = w * h;
    }

    if (i < BN) {
        g_maxam[i] = 0u; g_maxiou[i] = 0u;
        bool is64 = true;
        for (int j = 1; j < BN; j += 2) {
            if (glab32[j] != 0) { is64 = false; break; }
        }
        int lab = is64 ? glab32[2 * i] : glab32[i];
        lab = min(max(lab, 0), CC - 1);

        const float* p = gtb + (size_t)i * 5;
        float cx = p[0], cy = p[1], w = p[2], h = p[3], r = p[4];
        float mnx, mxx, mny, mxy;
        box_aabb(cx, cy, w, h, r, mnx, mxx, mny, mxy);
        g_gaabb[i] = make_float4(mnx, mxx, mny, mxy);
        g_garea[i] = w * h;
        g_gcos[i] = cosf(r);
        g_gsin[i] = sinf(r);
        g_gcx[i] = cx; g_gcy[i] = cy;
        g_gw2[i] = w * 0.5f; g_gh2[i] = h * 0.5f;
        g_glabel[i] = lab;
        g_gcrowd[i] = gcrowd[i];
        g_gpad[i] = gpad[i];
    }
}

// ---------------- K2: per-(b,gt) top-13 + scatter ----------------
__constant__ int   c_lG[3]    = {128, 64, 32};
__constant__ int   c_lbase[3] = {0, 16384, 20480};
__constant__ float c_ls[3]    = {8.0f, 16.0f, 32.0f};

__global__ void __launch_bounds__(256) k_topk(const float* __restrict__ scores,
                                              const float* __restrict__ anch) {
    const int bi = blockIdx.x;
    const int b = bi / NN;
    const int gi = bi % NN;
    const int tid = threadIdx.x;

    __shared__ float sg[9];
    __shared__ float sw2, sh2, spad;
    __shared__ int slab;
    __shared__ int scount;
    __shared__ unsigned long long sbuf[CAP];

    if (tid == 0) {
        float4 a = g_gaabb[bi];
        sg[0] = a.x; sg[1] = a.y; sg[2] = a.z; sg[3] = a.w;
        sg[4] = g_garea[bi];
        sg[5] = g_gcos[bi]; sg[6] = g_gsin[bi];
        sg[7] = g_gcx[bi];  sg[8] = g_gcy[bi];
        sw2 = g_gw2[bi]; sh2 = g_gh2[bi];
        slab = g_glabel[bi];
        spad = g_gpad[bi];
        scount = 0;
    }
    __syncthreads();
    if (spad == 0.0f) return;

    const float4 ga = make_float4(sg[0], sg[1], sg[2], sg[3]);
    const float garea = sg[4], gc = sg[5], gs = sg[6], gcx = sg[7], gcy = sg[8];
    const float w2 = sw2, h2 = sh2;
    const int lab = slab;
    const size_t sbase = (size_t)b * LL * CC;
    const int pbase = b * LL;
    const float2* anch2 = (const float2*)anch;

    // TRUE containment extents of the rbox interior
    const float Ex = w2 * fabsf(gc) + h2 * fabsf(gs);
    const float Ey = w2 * fabsf(gs) + h2 * fabsf(gc);
    const float rx0 = gcx - Ex, rx1 = gcx + Ex;
    const float ry0 = gcy - Ey, ry1 = gcy + Ey;

    unsigned long long loc[TK];
#pragma unroll
    for (int k = 0; k < TK; ++k) loc[k] = 0ull;

    for (int lev = 0; lev < 3; ++lev) {
        const float st = c_ls[lev];
        const int G = c_lG[lev];
        const int base = c_lbase[lev];
        const float inv = 1.0f / st;
        int ix0 = max(0, (int)floorf(rx0 * inv - 0.5f) - 1);
        int ix1 = min(G - 1, (int)ceilf(rx1 * inv - 0.5f) + 1);
        int iy0 = max(0, (int)floorf(ry0 * inv - 0.5f) - 1);
        int iy1 = min(G - 1, (int)ceilf(ry1 * inv - 0.5f) + 1);
        int nx = ix1 - ix0 + 1;
        int ny = iy1 - iy0 + 1;
        if (nx <= 0 || ny <= 0) continue;
        int tot = nx * ny;
        for (int t = tid; t < tot; t += 256) {
            int iy = iy0 + t / nx;
            int ix = ix0 + t - (t / nx) * nx;
            float px = ((float)ix + 0.5f) * st;
            float py = ((float)iy + 0.5f) * st;
            if (!pt_inside(px, py, gcx, gcy, gc, gs, w2, h2)) continue;
            int l = base + iy * G + ix;
            float4 pa = g_paabb[pbase + l];
            float iou = iou_ab(ga, garea, pa, g_parea[pbase + l]);
            float sc = scores[sbase + (size_t)l * CC + lab];
            float am = sc * pow6(iou);
            if (am <= 0.0f) continue;
            unsigned long long key =
                ((unsigned long long)__float_as_uint(am) << 32) |
                (unsigned long long)(0xFFFFFFFFu - (unsigned)l);
            insert13(loc, key);
        }
    }

    int cnt = 0;
#pragma unroll
    for (int k = 0; k < TK; ++k) if (loc[k] != 0ull) cnt++;
    if (cnt > 0) {
        int base = atomicAdd(&scount, cnt);
        int j = 0;
#pragma unroll
        for (int k = 0; k < TK; ++k)
            if (loc[k] != 0ull) sbuf[base + j++] = loc[k];
    }
    __syncthreads();
    if (tid >= 32) return;

    const unsigned FULL = 0xFFFFFFFFu;
    int n = scount;
    unsigned long long w13[TK];
#pragma unroll
    for (int k = 0; k < TK; ++k) w13[k] = 0ull;
    for (int i = tid; i < n; i += 32) insert13(w13, sbuf[i]);

    int fillc = 0;
    for (int r = 0; r < TK; ++r) {
        unsigned long long m = w13[TK - 1];
#pragma unroll
        for (int off = 16; off > 0; off >>= 1) {
            unsigned long long o = __shfl_xor_sync(FULL, m, off);
            m = (o > m) ? o : m;
        }
        if (m == 0ull) { fillc = TK - r; break; }
        bool own = (w13[TK - 1] == m);
        unsigned ob = __ballot_sync(FULL, own);
        if (tid == (__ffs(ob) - 1)) {
#pragma unroll
            for (int k = TK - 1; k > 0; --k) w13[k] = w13[k - 1];
            w13[0] = 0ull;
        }
        if (tid == 0) {
            unsigned anchor = 0xFFFFFFFFu - (unsigned)(m & 0xFFFFFFFFull);
            int a = pbase + anchor;
            int old = atomicAdd(&g_sum[a], 1);
            g_tmpg[a] = gi;
            if (old == 0) {
                int p = atomicAdd(&g_npos, 1);
                if (p < PLCAP) g_plist[p] = a;
            }
        }
    }

    if (fillc > 0) {
        int l = tid;
        float2 pt = anch2[l];
        bool ins = pt_inside(pt.x, pt.y, gcx, gcy, gc, gs, w2, h2);
        bool zero = true;
        if (ins) {
            float4 pa = g_paabb[pbase + l];
            float iou = iou_ab(ga, garea, pa, g_parea[pbase + l]);
            float sc = scores[sbase + (size_t)l * CC + lab];
            zero = (sc * pow6(iou) <= 0.0f);
        }
        unsigned zm = __ballot_sync(FULL, zero);
        unsigned im = __ballot_sync(FULL, ins);
        if (tid == 0) {
            for (int c = 0; c < fillc && zm; ++c) {
                int bpos = __ffs(zm) - 1;
                zm &= zm - 1;
                if ((im >> bpos) & 1u) {
                    int a = pbase + bpos;
                    int old = atomicAdd(&g_sum[a], 1);
                    g_tmpg[a] = gi;
                    if (old == 0) {
                        int p = atomicAdd(&g_npos, 1);
                        if (p < PLCAP) g_plist[p] = a;
                    }
                }
            }
        }
    }
}

// ---------------- K3: warp-per-positive assignment ----------------
__global__ void __launch_bounds__(256) k_assign(const float* __restrict__ scores) {
    int gtid = blockIdx.x * blockDim.x + threadIdx.x;
    int wi = gtid >> 5;
    int lane = gtid & 31;
    int np = g_npos;
    if (wi >= np) return;
    int a = g_plist[wi];
    int b = a / LL;
    int s = g_sum[a];
    float4 pa = g_paabb[a];
    float parea = g_parea[a];

    int g;
    if (s == 1) {
        g = g_tmpg[a];
    } else {
        const unsigned FULL = 0xFFFFFFFFu;
        unsigned long long best = 0ull;
#pragma unroll
        for (int h = 0; h < 2; ++h) {
            int i = lane + h * 32;
            if (i < NN) {
                int gg = b * NN + i;
                float iou = iou_ab(g_gaabb[gg], g_garea[gg], pa, parea);
                unsigned long long key =
                    ((unsigned long long)__float_as_uint(iou) << 32) |
                    (unsigned long long)(63 - i);
                best = (key > best) ? key : best;
            }
        }
#pragma unroll
        for (int off = 16; off > 0; off >>= 1) {
            unsigned long long o = __shfl_xor_sync(FULL, best, off);
            best = (o > best) ? o : best;
        }
        g = 63 - (int)(best & 0xFFFFFFFFull);
    }

    if (lane == 0) {
        int gg = b * NN + g;
        float iou = iou_ab(g_gaabb[gg], g_garea[gg], pa, parea);
        float sc = scores[(size_t)a * CC + g_glabel[gg]];
        float am = sc * pow6(iou);
        g_asg[a] = g;
        g_amv[a] = am;
        atomicMax(&g_maxam[gg], __float_as_uint(am));
        atomicMax(&g_maxiou[gg], __float_as_uint(iou));
    }
}

// ---------------- K4: outputs (float4-vectorized, fully coalesced) ----------------
// out layout: [lab BL][rb 5*BL][sc 15*BL][gi BL][cr BL] = 23*BL floats.
// All region boundaries are multiples of 4, so each float4 is single-region.
static constexpr int OUT_TOTAL = BL * 23;
static constexpr int OUT_Q = OUT_TOTAL / 4;

__global__ void __launch_bounds__(256) k_out(const float* __restrict__ gtb,
                                             float* __restrict__ out) {
    int q = blockIdx.x * blockDim.x + threadIdx.x;
    if (q >= OUT_Q) return;
    int e0 = q * 4;
    float4 v;
    float* vv = &v.x;

    if (e0 < BL) {                       // labels
#pragma unroll
        for (int u = 0; u < 4; ++u) {
            int idx = e0 + u;
            int s = g_sum[idx];
            int b = idx / LL;
            int g = (s > 0) ? g_asg[idx] : 0;
            int gg = b * NN + g;
            vv[u] = (float)((s > 0) ? g_glabel[gg] : BGI);
        }
    } else if (e0 < BL * 6) {            // rboxes
#pragma unroll
        for (int u = 0; u < 4; ++u) {
            int j = e0 + u - BL;
            int idx = j / 5;
            int k = j - idx * 5;
            int s = g_sum[idx];
            int b = idx / LL;
            int g = (s > 0) ? g_asg[idx] : 0;
            int gg = b * NN + g;
            vv[u] = gtb[(size_t)gg * 5 + k];
        }
    } else if (e0 < BL * 21) {           // scores
#pragma unroll
        for (int u = 0; u < 4; ++u) {
            int j = e0 + u - BL * 6;
            int idx = j / 15;
            int c = j - idx * 15;
            int s = g_sum[idx];
            float val = 0.0f;
            if (s > 0) {
                int b = idx / LL;
                int g = g_asg[idx];
                int gg = b * NN + g;
                if (c == g_glabel[gg] && g_gcrowd[gg] == 0) {
                    float mm = __uint_as_float(g_maxam[gg]);
                    float mi = __uint_as_float(g_maxiou[gg]);
                    val = g_amv[idx] / (mm + FEPS) * mi;
                }
            }
            vv[u] = val;
        }
    } else if (e0 < BL * 22) {           // gt index
#pragma unroll
        for (int u = 0; u < 4; ++u) {
            int idx = e0 + u - BL * 21;
            int s = g_sum[idx];
            vv[u] = (float)((s > 0) ? g_asg[idx] : 0);
        }
    } else {                             // crowd
#pragma unroll
        for (int u = 0; u < 4; ++u) {
            int idx = e0 + u - BL * 22;
            int s = g_sum[idx];
            int b = idx / LL;
            int g = (s > 0) ? g_asg[idx] : 0;
            int gg = b * NN + g;
            vv[u] = (float)g_gcrowd[gg];
        }
    }
    reinterpret_cast<float4*>(out)[q] = v;
}

// ---------------- launch ----------------
extern "C" void kernel_launch(void* const* d_in, const int* in_sizes, int n_in,
                              void* d_out, int out_size) {
    const float* pred_scores = (const float*)d_in[0];
    const float* pred_rboxes = (const float*)d_in[1];
    const float* anchors     = (const float*)d_in[2];
    const int*   gt_labels32 = (const int*)d_in[3];
    const float* gt_bboxes   = (const float*)d_in[4];
    const int*   gt_crowd    = (const int*)d_in[6];
    const float* pad_mask    = (const float*)d_in[7];
    float*       out         = (float*)d_out;

    const int T = 256;
    k_pre<<<(BL + T - 1) / T, T>>>(pred_rboxes, gt_bboxes, gt_labels32, gt_crowd, pad_mask);
    k_topk<<<BN, 256>>>(pred_scores, anchors);
    k_assign<<<(6240 * 32 + T - 1) / T, T>>>(pred_scores);
    k_out<<<(OUT_Q + T - 1) / T, T>>>(gt_bboxes, out);
}